// round 3
// baseline (speedup 1.0000x reference)
#include <cuda_runtime.h>

// Problem constants
#define B_  16
#define N_  64
#define S_  4
#define F0_ 8
#define C_  32

// Per-batch workspace in dynamic shared memory (~88.7 KB)
struct Smem {
    float U[N_][5][C_];      // U[i][s][x]; s=4 is bias-kernel slot   (40 KB)
    float root[N_][C_];      // root term per row                      (8 KB)
    float h[N_][C_];         // hidden activations h1                  (8 KB)
    float wT1[F0_][5][C_];   // layer-1 kernel weights, transposed     (5 KB)
    float wrs1[F0_][C_];     // layer-1 root weights                   (1 KB)
    float wT2[C_][5][C_];    // layer-2 kernel weights, transposed    (20 KB)
    float wrs2[C_][C_];      // layer-2 root weights                   (4 KB)
    float bs1[C_];
    float bs2[C_];
    float maskv[N_];
    float red[32];
};

__global__ __launch_bounds__(1024, 1)
void fused_gnn_kernel(const float* __restrict__ x,
                      const float* __restrict__ a,
                      const float* __restrict__ e,
                      const float* __restrict__ w1k, const float* __restrict__ b1k,
                      const float* __restrict__ w1r, const float* __restrict__ b1,
                      const float* __restrict__ w2k, const float* __restrict__ b2k,
                      const float* __restrict__ w2r, const float* __restrict__ b2,
                      const float* __restrict__ wd,  const float* __restrict__ bd,
                      float* __restrict__ out)
{
    extern __shared__ Smem smem[];
    Smem& s = *smem;

    const int b    = blockIdx.x;
    const int tid  = threadIdx.x;
    const int warp = tid >> 5;
    const int lane = tid & 31;

    const float* xb = x + (size_t)b * N_ * (F0_ + 1);
    const float* ab = a + (size_t)b * N_ * N_;
    const float* eb = e + (size_t)b * N_ * N_ * S_;

    const float wdv = wd[lane];   // dense-head weight for this channel

    // ------------------------------------------------------------------
    // Stage 0: cooperative weight staging (transposed so per-lane-x reads
    // are conflict-free LDS).
    //   wk[s*(C*FIN) + xx*FIN + yy] -> wT[yy][s][xx]
    // ------------------------------------------------------------------
    for (int g = tid; g < S_*C_*F0_; g += 1024) {
        int sI = g / (C_*F0_); int r = g - sI*(C_*F0_);
        int xx = r / F0_;      int yy = r - xx*F0_;
        s.wT1[yy][sI][xx] = w1k[g];
    }
    for (int g = tid; g < C_*F0_; g += 1024) {
        int xx = g / F0_, yy = g - xx*F0_;
        s.wT1[yy][4][xx] = b1k[g];
    }
    for (int g = tid; g < F0_*C_; g += 1024)
        (&s.wrs1[0][0])[g] = w1r[g];

    for (int g = tid; g < S_*C_*C_; g += 1024) {
        int sI = g / (C_*C_); int r = g - sI*(C_*C_);
        int xx = r / C_;      int yy = r - xx*C_;
        s.wT2[yy][sI][xx] = w2k[g];
    }
    for (int g = tid; g < C_*C_; g += 1024) {
        int xx = g / C_, yy = g - xx*C_;
        s.wT2[yy][4][xx] = b2k[g];
    }
    for (int g = tid; g < C_*C_; g += 1024)
        (&s.wrs2[0][0])[g] = w2r[g];

    if (tid < C_) { s.bs1[tid] = b1[tid]; s.bs2[tid] = b2[tid]; }
    __syncthreads();

    // ------------------------------------------------------------------
    // Stage 1: prep1. U[row,s,x] = Σ_y wT1[y][s][x]·x[row,y]; root likewise.
    // Warp handles 2 rows; lane = x channel.
    // ------------------------------------------------------------------
    #pragma unroll
    for (int r = 0; r < 2; r++) {
        const int row = warp * 2 + r;
        float xv = (lane <= F0_) ? xb[row*(F0_+1) + lane] : 0.f;
        if (lane == F0_) s.maskv[row] = xv;

        float a0 = 0.f, a1 = 0.f, a2 = 0.f, a3 = 0.f, a4 = 0.f;
        float rt = s.bs1[lane];
        #pragma unroll
        for (int y = 0; y < F0_; y++) {
            float hv = __shfl_sync(0xffffffffu, xv, y);
            a0 += s.wT1[y][0][lane] * hv;
            a1 += s.wT1[y][1][lane] * hv;
            a2 += s.wT1[y][2][lane] * hv;
            a3 += s.wT1[y][3][lane] * hv;
            a4 += s.wT1[y][4][lane] * hv;
            rt += s.wrs1[y][lane]   * hv;
        }
        s.U[row][0][lane] = a0;
        s.U[row][1][lane] = a1;
        s.U[row][2][lane] = a2;
        s.U[row][3][lane] = a3;
        s.U[row][4][lane] = a4;
        s.root[row][lane] = rt;
    }
    __syncthreads();

    // ------------------------------------------------------------------
    // Stage 2: msg1. Sparse gather over neighbors via ballot compaction.
    // Adjacency in registers, U/root in smem, e from gmem (L2).
    // ------------------------------------------------------------------
    #pragma unroll
    for (int r = 0; r < 2; r++) {
        const int row = warp * 2 + r;
        const float m = s.maskv[row];
        float acc = 0.f;
        float av0 = ab[(size_t)row * N_ + lane];
        float av1 = ab[(size_t)row * N_ + 32 + lane];
        unsigned nz0 = __ballot_sync(0xffffffffu, av0 != 0.f);
        unsigned nz1 = __ballot_sync(0xffffffffu, av1 != 0.f);
        if (m != 0.f) {
            const float4* erow = (const float4*)(eb + (size_t)row * N_ * S_);
            while (nz0) {
                int j = __ffs(nz0) - 1; nz0 &= nz0 - 1;
                float av = __shfl_sync(0xffffffffu, av0, j);
                float4 ev = erow[j];
                acc += (av*ev.x) * s.U[j][0][lane];
                acc += (av*ev.y) * s.U[j][1][lane];
                acc += (av*ev.z) * s.U[j][2][lane];
                acc += (av*ev.w) * s.U[j][3][lane];
                acc +=  av       * s.U[j][4][lane];
            }
            while (nz1) {
                int j = __ffs(nz1) - 1; nz1 &= nz1 - 1;
                int i = 32 + j;
                float av = __shfl_sync(0xffffffffu, av1, j);
                float4 ev = erow[i];
                acc += (av*ev.x) * s.U[i][0][lane];
                acc += (av*ev.y) * s.U[i][1][lane];
                acc += (av*ev.z) * s.U[i][2][lane];
                acc += (av*ev.w) * s.U[i][3][lane];
                acc +=  av       * s.U[i][4][lane];
            }
        }
        float val = (acc + s.root[row][lane]) * m;
        s.h[row][lane] = fmaxf(val, 0.f);
    }
    __syncthreads();

    // ------------------------------------------------------------------
    // Stage 3: prep2 (FIN = C = 32). Overwrites U/root in place.
    // ------------------------------------------------------------------
    #pragma unroll
    for (int r = 0; r < 2; r++) {
        const int row = warp * 2 + r;
        float hv_own = s.h[row][lane];

        float a0 = 0.f, a1 = 0.f, a2 = 0.f, a3 = 0.f, a4 = 0.f;
        float rt = s.bs2[lane];
        #pragma unroll
        for (int y = 0; y < C_; y++) {
            float hv = __shfl_sync(0xffffffffu, hv_own, y);
            a0 += s.wT2[y][0][lane] * hv;
            a1 += s.wT2[y][1][lane] * hv;
            a2 += s.wT2[y][2][lane] * hv;
            a3 += s.wT2[y][3][lane] * hv;
            a4 += s.wT2[y][4][lane] * hv;
            rt += s.wrs2[y][lane]   * hv;
        }
        s.U[row][0][lane] = a0;
        s.U[row][1][lane] = a1;
        s.U[row][2][lane] = a2;
        s.U[row][3][lane] = a3;
        s.U[row][4][lane] = a4;
        s.root[row][lane] = rt;
    }
    __syncthreads();

    // ------------------------------------------------------------------
    // Stage 4: msg2 + fused pool partial (out[b] = Σ_{t,x} h2[t,x]·wd[x]).
    // ------------------------------------------------------------------
    float pacc = 0.f;
    #pragma unroll
    for (int r = 0; r < 2; r++) {
        const int row = warp * 2 + r;
        const float m = s.maskv[row];
        float acc = 0.f;
        float av0 = ab[(size_t)row * N_ + lane];
        float av1 = ab[(size_t)row * N_ + 32 + lane];
        unsigned nz0 = __ballot_sync(0xffffffffu, av0 != 0.f);
        unsigned nz1 = __ballot_sync(0xffffffffu, av1 != 0.f);
        if (m != 0.f) {
            const float4* erow = (const float4*)(eb + (size_t)row * N_ * S_);
            while (nz0) {
                int j = __ffs(nz0) - 1; nz0 &= nz0 - 1;
                float av = __shfl_sync(0xffffffffu, av0, j);
                float4 ev = erow[j];
                acc += (av*ev.x) * s.U[j][0][lane];
                acc += (av*ev.y) * s.U[j][1][lane];
                acc += (av*ev.z) * s.U[j][2][lane];
                acc += (av*ev.w) * s.U[j][3][lane];
                acc +=  av       * s.U[j][4][lane];
            }
            while (nz1) {
                int j = __ffs(nz1) - 1; nz1 &= nz1 - 1;
                int i = 32 + j;
                float av = __shfl_sync(0xffffffffu, av1, j);
                float4 ev = erow[i];
                acc += (av*ev.x) * s.U[i][0][lane];
                acc += (av*ev.y) * s.U[i][1][lane];
                acc += (av*ev.z) * s.U[i][2][lane];
                acc += (av*ev.w) * s.U[i][3][lane];
                acc +=  av       * s.U[i][4][lane];
            }
        }
        float val = fmaxf((acc + s.root[row][lane]) * m, 0.f);
        pacc += val * wdv;
    }

    // Warp-reduce pool partial, then block-reduce.
    #pragma unroll
    for (int off = 16; off > 0; off >>= 1)
        pacc += __shfl_down_sync(0xffffffffu, pacc, off);
    if (lane == 0) s.red[warp] = pacc;
    __syncthreads();
    if (warp == 0) {
        float v = s.red[lane];
        #pragma unroll
        for (int off = 16; off > 0; off >>= 1)
            v += __shfl_down_sync(0xffffffffu, v, off);
        if (lane == 0) out[b] = v + bd[0];
    }
}

// ---------------------------------------------------------------------------
extern "C" void kernel_launch(void* const* d_in, const int* in_sizes, int n_in,
                              void* d_out, int out_size)
{
    const float* x       = (const float*)d_in[0];
    const float* a       = (const float*)d_in[1];
    const float* e       = (const float*)d_in[2];
    const float* w1_kern = (const float*)d_in[3];
    const float* b1_kern = (const float*)d_in[4];
    const float* w1_root = (const float*)d_in[5];
    const float* b1      = (const float*)d_in[6];
    const float* w2_kern = (const float*)d_in[7];
    const float* b2_kern = (const float*)d_in[8];
    const float* w2_root = (const float*)d_in[9];
    const float* b2      = (const float*)d_in[10];
    const float* w_dense = (const float*)d_in[11];
    const float* b_dense = (const float*)d_in[12];
    float* out = (float*)d_out;

    // >48KB dynamic smem requires the opt-in attribute (idempotent; not a
    // stream-ordered call, safe under graph capture).
    cudaFuncSetAttribute(fused_gnn_kernel,
                         cudaFuncAttributeMaxDynamicSharedMemorySize,
                         (int)sizeof(Smem));

    fused_gnn_kernel<<<B_, 1024, sizeof(Smem)>>>(
        x, a, e,
        w1_kern, b1_kern, w1_root, b1,
        w2_kern, b2_kern, w2_root, b2,
        w_dense, b_dense, out);
}

// round 4
// speedup vs baseline: 1.9118x; 1.9118x over previous
#include <cuda_runtime.h>

// Problem constants
#define B_  16
#define N_  64
#define S_  4
#define F0_ 8
#define C_  32
#define G_  4          // CTAs per batch (channel slices)
#define XL_ 8          // channels per slice (C_/G_)

// Cross-CTA pool combine scratch
__device__ float    g_part[B_ * G_];
__device__ unsigned g_cnt[B_];        // zero-init; atomicInc wraps -> 0 each call

// Per-CTA shared workspace (~82 KB)
struct Smem {
    float wT1[F0_][5][C_];   // layer1 kernel weights transposed [y][s][x] (s=4: b1_kern)
    float wrs1[F0_][C_];     // layer1 root weights [y][x]
    float U1[N_][5][C_];     // layer1 per-node projections (full)
    float root1[N_][C_];
    float h1[N_][C_];
    float w2s[C_][32];       // layer2 kernel slice [y][s*8+xl]
    float w2br[C_][16];      // [y][0..7: b2_kern slice, 8..15: w2_root slice]
    float U2[N_][32];        // [i][s*8+xl]
    float U2br[N_][16];      // [i][0..7: bias-kernel slot, 8..15: root2]
    float bs1[C_];
    float bs2s[XL_];
    float maskv[N_];
    float red[32];
};

__global__ __launch_bounds__(1024, 1)
void fused_gnn_kernel(const float* __restrict__ x,
                      const float* __restrict__ a,
                      const float* __restrict__ e,
                      const float* __restrict__ w1k, const float* __restrict__ b1k,
                      const float* __restrict__ w1r, const float* __restrict__ b1,
                      const float* __restrict__ w2k, const float* __restrict__ b2k,
                      const float* __restrict__ w2r, const float* __restrict__ b2,
                      const float* __restrict__ wd,  const float* __restrict__ bd,
                      float* __restrict__ out)
{
    extern __shared__ Smem smem[];
    Smem& s = *smem;

    const int b    = blockIdx.x >> 2;     // batch
    const int g    = blockIdx.x & 3;      // channel slice
    const int tid  = threadIdx.x;
    const int warp = tid >> 5;
    const int lane = tid & 31;

    const float* xb = x + (size_t)b * N_ * (F0_ + 1);
    const float* ab = a + (size_t)b * N_ * N_;
    const float* eb = e + (size_t)b * N_ * N_ * S_;

    // ------------------------------------------------------------------
    // Stage 0: weight staging
    // ------------------------------------------------------------------
    for (int i0 = tid; i0 < S_*C_*F0_; i0 += 1024) {
        int sI = i0 / (C_*F0_); int r = i0 - sI*(C_*F0_);
        int xx = r / F0_;       int yy = r - xx*F0_;
        s.wT1[yy][sI][xx] = w1k[i0];
    }
    for (int i0 = tid; i0 < C_*F0_; i0 += 1024) {
        int xx = i0 / F0_, yy = i0 - xx*F0_;
        s.wT1[yy][4][xx] = b1k[i0];
    }
    for (int i0 = tid; i0 < F0_*C_; i0 += 1024)
        (&s.wrs1[0][0])[i0] = w1r[i0];

    // layer2 slice: w2s[y][s*8+xl] = w2k[s*(C*C) + (g*8+xl)*C + y]
    {
        int yy = tid & 31, l = tid >> 5;      // 1024 threads: one element each
        int sI = l >> 3,   xl = l & 7;
        s.w2s[yy][l] = w2k[sI*(C_*C_) + (g*XL_ + xl)*C_ + yy];
    }
    if (tid < 512) {
        int yy = tid & 31, l = tid >> 5;      // l in 0..15
        float v;
        if (l < 8) v = b2k[(g*XL_ + l)*C_ + yy];           // bias-kernel slot
        else       v = w2r[yy*C_ + g*XL_ + (l - 8)];       // root weights
        s.w2br[yy][l] = v;
    }
    if (tid < XL_) s.bs2s[tid] = b2[g*XL_ + tid];
    if (tid < C_)  s.bs1[tid]  = b1[tid];
    __syncthreads();

    // ------------------------------------------------------------------
    // Stage 1: prep1 (full, redundant per slice-CTA). 2 rows/warp, lane=x.
    // ------------------------------------------------------------------
    #pragma unroll
    for (int r = 0; r < 2; r++) {
        const int row = warp*2 + r;
        float xv = (lane <= F0_) ? xb[row*(F0_+1) + lane] : 0.f;
        if (lane == F0_) s.maskv[row] = xv;

        float a0=0.f, a1=0.f, a2=0.f, a3=0.f, a4=0.f;
        float rt = s.bs1[lane];
        #pragma unroll
        for (int y = 0; y < F0_; y++) {
            float hv = __shfl_sync(0xffffffffu, xv, y);
            a0 += s.wT1[y][0][lane] * hv;
            a1 += s.wT1[y][1][lane] * hv;
            a2 += s.wT1[y][2][lane] * hv;
            a3 += s.wT1[y][3][lane] * hv;
            a4 += s.wT1[y][4][lane] * hv;
            rt += s.wrs1[y][lane]   * hv;
        }
        s.U1[row][0][lane] = a0;
        s.U1[row][1][lane] = a1;
        s.U1[row][2][lane] = a2;
        s.U1[row][3][lane] = a3;
        s.U1[row][4][lane] = a4;
        s.root1[row][lane] = rt;
    }
    __syncthreads();

    // ------------------------------------------------------------------
    // Stage 2: msg1 (full). Ballot-compacted sparse gather, U1 in smem.
    // ------------------------------------------------------------------
    #pragma unroll
    for (int r = 0; r < 2; r++) {
        const int row = warp*2 + r;
        const float m = s.maskv[row];
        float av0 = ab[(size_t)row*N_ + lane];
        float av1 = ab[(size_t)row*N_ + 32 + lane];
        unsigned nz0 = __ballot_sync(0xffffffffu, av0 != 0.f);
        unsigned nz1 = __ballot_sync(0xffffffffu, av1 != 0.f);
        float acc = 0.f;
        if (m != 0.f) {
            const float4* erow = (const float4*)(eb + (size_t)row * N_ * S_);
            while (nz0) {
                int j = __ffs(nz0) - 1; nz0 &= nz0 - 1;
                float av = __shfl_sync(0xffffffffu, av0, j);
                float4 ev = erow[j];
                acc += (av*ev.x) * s.U1[j][0][lane];
                acc += (av*ev.y) * s.U1[j][1][lane];
                acc += (av*ev.z) * s.U1[j][2][lane];
                acc += (av*ev.w) * s.U1[j][3][lane];
                acc +=  av       * s.U1[j][4][lane];
            }
            while (nz1) {
                int j = __ffs(nz1) - 1; nz1 &= nz1 - 1;
                int i = 32 + j;
                float av = __shfl_sync(0xffffffffu, av1, j);
                float4 ev = erow[i];
                acc += (av*ev.x) * s.U1[i][0][lane];
                acc += (av*ev.y) * s.U1[i][1][lane];
                acc += (av*ev.z) * s.U1[i][2][lane];
                acc += (av*ev.w) * s.U1[i][3][lane];
                acc +=  av       * s.U1[i][4][lane];
            }
        }
        s.h1[row][lane] = fmaxf((acc + s.root1[row][lane]) * m, 0.f);
    }
    __syncthreads();

    // ------------------------------------------------------------------
    // Stage 3: prep2 (slice). Warp owns rows (2w, 2w+1).
    // Main acc: lane = s*8+xl computes U2[row][s][xl].
    // Aux acc: lanes split by (lane>>4) into the two rows; (lane&15):
    //          0..7 bias-kernel slot, 8..15 root2.
    // ------------------------------------------------------------------
    {
        const int row0 = warp*2, row1 = row0 + 1;
        float h0 = s.h1[row0][lane];
        float h1v = s.h1[row1][lane];
        float accA = 0.f, accB = 0.f;
        float acc2 = ((lane & 15) >= 8) ? s.bs2s[lane & 7] : 0.f;
        #pragma unroll
        for (int y = 0; y < C_; y++) {
            float w   = s.w2s[y][lane];
            float hv0 = __shfl_sync(0xffffffffu, h0,  y);
            float hv1 = __shfl_sync(0xffffffffu, h1v, y);
            accA += w * hv0;
            accB += w * hv1;
            float wbr  = s.w2br[y][lane & 15];
            float hsel = (lane < 16) ? hv0 : hv1;
            acc2 += wbr * hsel;
        }
        s.U2[row0][lane] = accA;
        s.U2[row1][lane] = accB;
        s.U2br[row0 + (lane >> 4)][lane & 15] = acc2;
    }
    __syncthreads();

    // ------------------------------------------------------------------
    // Stage 4: msg2 (slice) + fused pool partial.
    // lane = s-group (lane>>3) x channel (lane&7).
    // ------------------------------------------------------------------
    float pacc = 0.f;
    const float wdv  = wd[g*XL_ + (lane & 7)];
    const int   sidx = lane >> 3;
    #pragma unroll
    for (int r = 0; r < 2; r++) {
        const int row = warp*2 + r;
        const float m = s.maskv[row];
        float av0 = ab[(size_t)row*N_ + lane];
        float av1 = ab[(size_t)row*N_ + 32 + lane];
        unsigned nz0 = __ballot_sync(0xffffffffu, av0 != 0.f);
        unsigned nz1 = __ballot_sync(0xffffffffu, av1 != 0.f);
        float acc = 0.f, accb = 0.f;
        if (m != 0.f) {
            const float* erowf = eb + (size_t)row * N_ * S_;
            while (nz0) {
                int j = __ffs(nz0) - 1; nz0 &= nz0 - 1;
                float av = __shfl_sync(0xffffffffu, av0, j);
                float ev = erowf[j*S_ + sidx];
                acc  += (av*ev) * s.U2[j][lane];
                accb +=  av     * s.U2br[j][lane & 7];
            }
            while (nz1) {
                int j = __ffs(nz1) - 1; nz1 &= nz1 - 1;
                int i = 32 + j;
                float av = __shfl_sync(0xffffffffu, av1, j);
                float ev = erowf[i*S_ + sidx];
                acc  += (av*ev) * s.U2[i][lane];
                accb +=  av     * s.U2br[i][lane & 7];
            }
        }
        // fold the 4 s-groups (accb is already identical across groups)
        acc += __shfl_xor_sync(0xffffffffu, acc, 8);
        acc += __shfl_xor_sync(0xffffffffu, acc, 16);
        float rt  = s.U2br[row][8 + (lane & 7)];
        float val = fmaxf((acc + accb + rt) * m, 0.f);
        if (lane < 8) pacc += val * wdv;     // count each channel once
    }

    // block-reduce pool partial
    #pragma unroll
    for (int off = 16; off > 0; off >>= 1)
        pacc += __shfl_down_sync(0xffffffffu, pacc, off);
    if (lane == 0) s.red[warp] = pacc;
    __syncthreads();
    if (warp == 0) {
        float v = s.red[lane];
        #pragma unroll
        for (int off = 16; off > 0; off >>= 1)
            v += __shfl_down_sync(0xffffffffu, v, off);
        if (lane == 0) {
            g_part[b*G_ + g] = v;
            __threadfence();
            unsigned t = atomicInc(&g_cnt[b], G_ - 1u);   // wraps to 0 each call
            if (t == G_ - 1u) {
                volatile float* p = g_part + b*G_;
                out[b] = p[0] + p[1] + p[2] + p[3] + bd[0];
            }
        }
    }
}

// ---------------------------------------------------------------------------
extern "C" void kernel_launch(void* const* d_in, const int* in_sizes, int n_in,
                              void* d_out, int out_size)
{
    const float* x       = (const float*)d_in[0];
    const float* a       = (const float*)d_in[1];
    const float* e       = (const float*)d_in[2];
    const float* w1_kern = (const float*)d_in[3];
    const float* b1_kern = (const float*)d_in[4];
    const float* w1_root = (const float*)d_in[5];
    const float* b1      = (const float*)d_in[6];
    const float* w2_kern = (const float*)d_in[7];
    const float* b2_kern = (const float*)d_in[8];
    const float* w2_root = (const float*)d_in[9];
    const float* b2      = (const float*)d_in[10];
    const float* w_dense = (const float*)d_in[11];
    const float* b_dense = (const float*)d_in[12];
    float* out = (float*)d_out;

    cudaFuncSetAttribute(fused_gnn_kernel,
                         cudaFuncAttributeMaxDynamicSharedMemorySize,
                         (int)sizeof(Smem));

    fused_gnn_kernel<<<B_*G_, 1024, sizeof(Smem)>>>(
        x, a, e,
        w1_kern, b1_kern, w1_root, b1,
        w2_kern, b2_kern, w2_root, b2,
        w_dense, b_dense, out);
}